// round 9
// baseline (speedup 1.0000x reference)
#include <cuda_runtime.h>

#define F_IN 1433
#define F1   16
#define F2   7
#define NMAX 50000
#define EMAX 1664000
#define KPAD 1440

// ---------------- scratch (no allocations allowed) ----------------
__device__ __align__(16) int   g_cnt [NMAX];     // in-degree (real edges)
__device__ __align__(16) int   g_off [NMAX];     // CSR bucket start
__device__ __align__(16) int   g_cur [NMAX];     // fill cursor
__device__             int     g_total;          // bucket allocator
__device__ __align__(16) int   g_srcs[EMAX];     // CSR: src per in-edge, bucketed by dst
__device__ __align__(16) float g_dinv[NMAX];
__device__ __align__(16) float g_hs1 [NMAX * 16];  // x@W1 (raw), then *dinv after k_scale
__device__ __align__(16) float g_hs2 [NMAX * 8];   // (a1@W2)*dinv (gather source L2, col7=0)

// packed fp32x2 FMA (Blackwell; only reachable via PTX)
#define FMA2(d,a,b,c) asm("fma.rn.f32x2 %0, %1, %2, %3;" : "=l"(d) : "l"(a), "l"(b), "l"(c))

// ---------------- CSR build ----------------
__global__ __launch_bounds__(256) void k_count(const int* __restrict__ ei, int E) {
    int i  = blockIdx.x * blockDim.x + threadIdx.x;
    int E4 = E >> 2;
    if (i < E4) {
        int4 d = ((const int4*)(ei + E))[i];
        atomicAdd(&g_cnt[d.x], 1);
        atomicAdd(&g_cnt[d.y], 1);
        atomicAdd(&g_cnt[d.z], 1);
        atomicAdd(&g_cnt[d.w], 1);
    }
    if (i == 0)
        for (int e = E4 << 2; e < E; ++e) atomicAdd(&g_cnt[ei[E + e]], 1);
}

// bucket offsets via warp scan + one global atomic (order of buckets irrelevant)
__global__ __launch_bounds__(256) void k_alloc(int n) {
    int i    = blockIdx.x * blockDim.x + threadIdx.x;
    int lane = threadIdx.x & 31;
    int c    = (i < n) ? g_cnt[i] : 0;
    int incl = c;
    #pragma unroll
    for (int o = 1; o < 32; o <<= 1) {
        int v = __shfl_up_sync(0xffffffffu, incl, o);
        if (lane >= o) incl += v;
    }
    int tot  = __shfl_sync(0xffffffffu, incl, 31);
    int base = 0;
    if (lane == 31) base = atomicAdd(&g_total, tot);
    base = __shfl_sync(0xffffffffu, base, 31);
    if (i < n) {
        int off = base + incl - c;
        g_off[i] = off;
        g_cur[i] = off;
        g_dinv[i] = rsqrtf((float)(c + 1));   // +1 self loop
    }
}

__global__ __launch_bounds__(256) void k_fill(const int* __restrict__ ei, int E) {
    int i  = blockIdx.x * blockDim.x + threadIdx.x;
    int E4 = E >> 2;
    if (i < E4) {
        int4 s = ((const int4*)ei)[i];
        int4 d = ((const int4*)(ei + E))[i];
        int p0 = atomicAdd(&g_cur[d.x], 1);
        int p1 = atomicAdd(&g_cur[d.y], 1);
        int p2 = atomicAdd(&g_cur[d.z], 1);
        int p3 = atomicAdd(&g_cur[d.w], 1);
        g_srcs[p0] = s.x; g_srcs[p1] = s.y; g_srcs[p2] = s.z; g_srcs[p3] = s.w;
    }
    if (i == 0)
        for (int e = E4 << 2; e < E; ++e) {
            int p = atomicAdd(&g_cur[ei[E + e]], 1);
            g_srcs[p] = ei[e];
        }
}

// ---------------- GEMM1: hs1 = x @ W1 (raw; dinv applied by k_scale) ----------------
#define G1_BLK  192
#define G1_GRID 296                       // 2 blocks/SM exactly
#define G1_ROWS 169                       // ceil(50000/296)

__global__ __launch_bounds__(G1_BLK) void k_gemm1(const float* __restrict__ x,
                                                  const float* __restrict__ W1, int n)
{
    extern __shared__ float w1s[];        // [KPAD][16] zero-padded
    int tid = threadIdx.x;
    for (int i = tid; i < KPAD * F1; i += G1_BLK)
        w1s[i] = (i < F_IN * F1) ? W1[i] : 0.0f;
    __syncthreads();

    int row = blockIdx.x * G1_ROWS + tid;
    if (tid >= G1_ROWS || row >= n) return;
    const float* xr = x + (size_t)row * F_IN;

    unsigned long long acc[8];
    #pragma unroll
    for (int j = 0; j < 8; ++j) acc[j] = 0ULL;

    for (int k0 = 0; k0 < F_IN; k0 += 16) {
        float xb[16];
        #pragma unroll
        for (int u = 0; u < 16; ++u) {
            int k = k0 + u;
            xb[u] = (k < F_IN) ? xr[k] : 0.0f;
        }
        #pragma unroll
        for (int u = 0; u < 16; ++u) {
            unsigned long long xx;
            asm("mov.b64 %0, {%1, %1};" : "=l"(xx) : "f"(xb[u]));
            const ulonglong2* wp = (const ulonglong2*)(w1s + (k0 + u) * F1);
            ulonglong2 wa = wp[0], wb = wp[1], wc = wp[2], wd = wp[3];
            FMA2(acc[0], wa.x, xx, acc[0]);
            FMA2(acc[1], wa.y, xx, acc[1]);
            FMA2(acc[2], wb.x, xx, acc[2]);
            FMA2(acc[3], wb.y, xx, acc[3]);
            FMA2(acc[4], wc.x, xx, acc[4]);
            FMA2(acc[5], wc.y, xx, acc[5]);
            FMA2(acc[6], wd.x, xx, acc[6]);
            FMA2(acc[7], wd.y, xx, acc[7]);
        }
    }

    float4* hp = (float4*)(g_hs1 + (size_t)row * 16);
    #pragma unroll
    for (int q = 0; q < 4; ++q) {
        union { unsigned long long u; float2 f; } a, b;
        a.u = acc[2 * q]; b.u = acc[2 * q + 1];
        hp[q] = make_float4(a.f.x, a.f.y, b.f.x, b.f.y);
    }
}

// ---------------- scale: hs1 *= dinv[row]  (runs after alloc+gemm1, overlaps fill) ----------------
__global__ __launch_bounds__(256) void k_scale(int n) {
    int r = blockIdx.x * blockDim.x + threadIdx.x;
    if (r >= n) return;
    float di = g_dinv[r];
    float4* hp = (float4*)(g_hs1 + (size_t)r * 16);
    #pragma unroll
    for (int q = 0; q < 4; ++q) {
        float4 v = hp[q];
        hp[q] = make_float4(v.x * di, v.y * di, v.z * di, v.w * di);
    }
}

// ---------------- gather L1 + bias/ReLU + layer2 GEMM (fused) ----------------
// warp per node; 8 edge-groups x 4 lanes (float4 column each); xor-reduce so
// all lanes hold their column sum; shfl-broadcast a1 row; 7 lanes apply W2.
__global__ __launch_bounds__(256) void k_gather16(const float* __restrict__ b1,
                                                  const float* __restrict__ W2, int n) {
    __shared__ float w2s[F1 * F2];
    if (threadIdx.x < F1 * F2) w2s[threadIdx.x] = W2[threadIdx.x];
    __syncthreads();

    int wid  = threadIdx.x >> 5;
    int lane = threadIdx.x & 31;
    int d    = blockIdx.x * 8 + wid;
    if (d >= n) return;

    int base = g_off[d];
    int cnt  = g_cnt[d];
    int grp  = lane >> 2;
    int col  = lane & 3;

    float4 acc = make_float4(0.f, 0.f, 0.f, 0.f);
    for (int it = grp; it < cnt; it += 8) {
        int s = g_srcs[base + it];
        float4 v = ((const float4*)(g_hs1 + (size_t)s * 16))[col];
        acc.x += v.x; acc.y += v.y; acc.z += v.z; acc.w += v.w;
    }
    __syncwarp();
    #pragma unroll
    for (int o = 16; o >= 4; o >>= 1) {
        acc.x += __shfl_xor_sync(0xffffffffu, acc.x, o);
        acc.y += __shfl_xor_sync(0xffffffffu, acc.y, o);
        acc.z += __shfl_xor_sync(0xffffffffu, acc.z, o);
        acc.w += __shfl_xor_sync(0xffffffffu, acc.w, o);
    }
    // every lane now holds the column sum for col = lane&3
    float  di   = g_dinv[d];
    float4 self = ((const float4*)(g_hs1 + (size_t)d * 16))[col];
    float4 b    = __ldg((const float4*)b1 + col);
    float4 o;
    o.x = fmaxf(fmaf(di, acc.x + self.x, b.x), 0.f);
    o.y = fmaxf(fmaf(di, acc.y + self.y, b.y), 0.f);
    o.z = fmaxf(fmaf(di, acc.z + self.z, b.z), 0.f);
    o.w = fmaxf(fmaf(di, acc.w + self.w, b.w), 0.f);

    // broadcast full a1 row: feature j lives in lane (j>>2), component (j&3)
    float a[F1];
    #pragma unroll
    for (int j = 0; j < F1; ++j) {
        float c;
        switch (j & 3) { case 0: c = o.x; break; case 1: c = o.y; break;
                         case 2: c = o.z; break; default: c = o.w; }
        a[j] = __shfl_sync(0xffffffffu, c, j >> 2);
    }
    if (lane < 8) {
        float v = 0.f;
        if (lane < 7) {
            float h = 0.f;
            #pragma unroll
            for (int j = 0; j < F1; ++j) h = fmaf(a[j], w2s[j * F2 + lane], h);
            v = h * di;
        }
        g_hs2[(size_t)d * 8 + lane] = v;
    }
}

// ---------------- gather L2 + bias + log_softmax (fused) ----------------
__global__ __launch_bounds__(256) void k_gather8f(const float* __restrict__ b2,
                                                  float* __restrict__ out, int n) {
    int wid  = threadIdx.x >> 5;
    int lane = threadIdx.x & 31;
    int d    = blockIdx.x * 8 + wid;
    if (d >= n) return;

    int base = g_off[d];
    int cnt  = g_cnt[d];
    int grp  = lane >> 1;
    int half = lane & 1;

    float4 acc = make_float4(0.f, 0.f, 0.f, 0.f);
    for (int it = grp; it < cnt; it += 16) {
        int s = g_srcs[base + it];
        float4 v = ((const float4*)(g_hs2 + (size_t)s * 8))[half];
        acc.x += v.x; acc.y += v.y; acc.z += v.z; acc.w += v.w;
    }
    __syncwarp();
    #pragma unroll
    for (int o = 16; o >= 2; o >>= 1) {
        acc.x += __shfl_down_sync(0xffffffffu, acc.x, o);
        acc.y += __shfl_down_sync(0xffffffffu, acc.y, o);
        acc.z += __shfl_down_sync(0xffffffffu, acc.z, o);
        acc.w += __shfl_down_sync(0xffffffffu, acc.w, o);
    }
    if (lane < 2) {
        float4 self = ((const float4*)(g_hs2 + (size_t)d * 8))[lane];
        acc.x += self.x; acc.y += self.y; acc.z += self.z; acc.w += self.w;
    }
    float hx = __shfl_sync(0xffffffffu, acc.x, 1);
    float hy = __shfl_sync(0xffffffffu, acc.y, 1);
    float hz = __shfl_sync(0xffffffffu, acc.z, 1);
    if (lane == 0) {
        float di = g_dinv[d];
        float v[7] = {acc.x, acc.y, acc.z, acc.w, hx, hy, hz};
        #pragma unroll
        for (int k = 0; k < 7; ++k) v[k] = fmaf(di, v[k], __ldg(b2 + k));
        float m = v[0];
        #pragma unroll
        for (int k = 1; k < 7; ++k) m = fmaxf(m, v[k]);
        float s = 0.f;
        #pragma unroll
        for (int k = 0; k < 7; ++k) s += expf(v[k] - m);
        float l = m + logf(s);
        float* op = out + (size_t)d * 7;
        #pragma unroll
        for (int k = 0; k < 7; ++k) op[k] = v[k] - l;
    }
}

// ---------------- launch ----------------
extern "C" void kernel_launch(void* const* d_in, const int* in_sizes, int n_in,
                              void* d_out, int out_size)
{
    const float* x  = (const float*)d_in[0];
    const int*   ei = (const int*)d_in[1];     // int32 (JAX x64 disabled)
    const float* W1 = (const float*)d_in[2];
    const float* b1 = (const float*)d_in[3];
    const float* W2 = (const float*)d_in[4];
    const float* b2 = (const float*)d_in[5];

    int n = in_sizes[0] / F_IN;   // 50000
    int E = in_sizes[1] / 2;      // 1600000

    const int smem1 = KPAD * F1 * (int)sizeof(float);   // 92160 B
    cudaFuncSetAttribute(k_gemm1, cudaFuncAttributeMaxDynamicSharedMemorySize, smem1);

    void* p_cnt = 0; void* p_total = 0;
    cudaGetSymbolAddress(&p_cnt, g_cnt);
    cudaGetSymbolAddress(&p_total, g_total);

    // one-time aux stream + events for fork/join inside graph capture
    static cudaStream_t s_aux = 0;
    static cudaEvent_t  ev_start = 0, ev_alloc = 0, ev_join = 0;
    if (!s_aux) {
        if (cudaStreamCreateWithFlags(&s_aux, cudaStreamNonBlocking) != cudaSuccess) s_aux = 0;
        if (s_aux) {
            cudaEventCreateWithFlags(&ev_start, cudaEventDisableTiming);
            cudaEventCreateWithFlags(&ev_alloc, cudaEventDisableTiming);
            cudaEventCreateWithFlags(&ev_join,  cudaEventDisableTiming);
        }
    }

    int nb256 = (n + 255) / 256;
    int e4b   = ((E >> 2) + 255) / 256;
    int gwarp = (n + 7) / 8;

    if (s_aux) {
        cudaEventRecord(ev_start, 0);
        cudaStreamWaitEvent(s_aux, ev_start, 0);
        // aux branch: heavy GEMM, then (after alloc) the dinv scale
        k_gemm1<<<G1_GRID, G1_BLK, smem1, s_aux>>>(x, W1, n);
        // main branch: CSR build
        cudaMemsetAsync(p_cnt, 0, NMAX * sizeof(int), 0);
        cudaMemsetAsync(p_total, 0, sizeof(int), 0);
        k_count<<<e4b, 256>>>(ei, E);
        k_alloc<<<nb256, 256>>>(n);
        cudaEventRecord(ev_alloc, 0);
        cudaStreamWaitEvent(s_aux, ev_alloc, 0);
        k_scale<<<nb256, 256, 0, s_aux>>>(n);          // overlaps k_fill
        cudaEventRecord(ev_join, s_aux);
        k_fill<<<e4b, 256>>>(ei, E);
        cudaStreamWaitEvent(0, ev_join, 0);
        k_gather16<<<gwarp, 256>>>(b1, W2, n);
        k_gather8f<<<gwarp, 256>>>(b2, (float*)d_out, n);
    } else {
        // serial fallback
        cudaMemsetAsync(p_cnt, 0, NMAX * sizeof(int), 0);
        cudaMemsetAsync(p_total, 0, sizeof(int), 0);
        k_count<<<e4b, 256>>>(ei, E);
        k_alloc<<<nb256, 256>>>(n);
        k_gemm1<<<G1_GRID, G1_BLK, smem1>>>(x, W1, n);
        k_scale<<<nb256, 256>>>(n);
        k_fill<<<e4b, 256>>>(ei, E);
        k_gather16<<<gwarp, 256>>>(b1, W2, n);
        k_gather8f<<<gwarp, 256>>>(b2, (float*)d_out, n);
    }
}

// round 11
// speedup vs baseline: 1.0124x; 1.0124x over previous
#include <cuda_runtime.h>

#define F_IN 1433
#define F1   16
#define F2   7
#define NMAX 50000
#define EMAX 1664000
#define KPAD 1440

// ---------------- scratch (no allocations allowed) ----------------
__device__ __align__(16) int   g_cnt [NMAX];     // in-degree (real edges)
__device__ __align__(16) int   g_off [NMAX];     // CSR bucket start
__device__ __align__(16) int   g_cur [NMAX];     // fill cursor
__device__             int     g_total;          // bucket allocator
__device__ __align__(16) int   g_srcs[EMAX];     // CSR: src per in-edge, bucketed by dst
__device__ __align__(16) float g_dinv[NMAX];
__device__ __align__(16) float g_hs1 [NMAX * 16];  // (x@W1)*dinv  (gather source L1)
__device__ __align__(16) float g_hs2 [NMAX * 8];   // (a1@W2)*dinv (gather source L2, col7=0)

// packed fp32x2 FMA (Blackwell; only reachable via PTX)
#define FMA2(d,a,b,c) asm("fma.rn.f32x2 %0, %1, %2, %3;" : "=l"(d) : "l"(a), "l"(b), "l"(c))

// ---------------- CSR build ----------------
__global__ __launch_bounds__(256) void k_count(const int* __restrict__ ei, int E) {
    int i  = blockIdx.x * blockDim.x + threadIdx.x;
    int E4 = E >> 2;
    if (i < E4) {
        int4 d = ((const int4*)(ei + E))[i];
        atomicAdd(&g_cnt[d.x], 1);
        atomicAdd(&g_cnt[d.y], 1);
        atomicAdd(&g_cnt[d.z], 1);
        atomicAdd(&g_cnt[d.w], 1);
    }
    if (i == 0)
        for (int e = E4 << 2; e < E; ++e) atomicAdd(&g_cnt[ei[E + e]], 1);
}

// bucket offsets via warp scan + one global atomic (order of buckets irrelevant)
__global__ __launch_bounds__(256) void k_alloc(int n) {
    int i    = blockIdx.x * blockDim.x + threadIdx.x;
    int lane = threadIdx.x & 31;
    int c    = (i < n) ? g_cnt[i] : 0;
    int incl = c;
    #pragma unroll
    for (int o = 1; o < 32; o <<= 1) {
        int v = __shfl_up_sync(0xffffffffu, incl, o);
        if (lane >= o) incl += v;
    }
    int tot  = __shfl_sync(0xffffffffu, incl, 31);
    int base = 0;
    if (lane == 31) base = atomicAdd(&g_total, tot);
    base = __shfl_sync(0xffffffffu, base, 31);
    if (i < n) {
        int off = base + incl - c;
        g_off[i] = off;
        g_cur[i] = off;
        g_dinv[i] = rsqrtf((float)(c + 1));   // +1 self loop
    }
}

__global__ __launch_bounds__(256) void k_fill(const int* __restrict__ ei, int E) {
    int i  = blockIdx.x * blockDim.x + threadIdx.x;
    int E4 = E >> 2;
    if (i < E4) {
        int4 s = ((const int4*)ei)[i];
        int4 d = ((const int4*)(ei + E))[i];
        int p0 = atomicAdd(&g_cur[d.x], 1);
        int p1 = atomicAdd(&g_cur[d.y], 1);
        int p2 = atomicAdd(&g_cur[d.z], 1);
        int p3 = atomicAdd(&g_cur[d.w], 1);
        g_srcs[p0] = s.x; g_srcs[p1] = s.y; g_srcs[p2] = s.z; g_srcs[p3] = s.w;
    }
    if (i == 0)
        for (int e = E4 << 2; e < E; ++e) {
            int p = atomicAdd(&g_cur[ei[E + e]], 1);
            g_srcs[p] = ei[e];
        }
}

// ---------------- GEMM1 v3: hs1 = (x @ W1) * dinv ----------------
// 384 thr (12 warps), 384 rows/block, grid=131 (single wave).
// W1 in smem (broadcast LDS.128); x staged coalesced -> transposed double-
// buffered tile xs[32][ROWP] (bank-stride 5, conflict-free both ways);
// register-carried tile t+1 overlaps compute of tile t.
#define G1_BLK  384
#define G1_RT   384
#define G1_GRID 131
#define KT      32
#define NT      45            // ceil(1433/32)
#define ROWP    389           // 389 % 32 = 5 -> conflict-free transpose store

__global__ __launch_bounds__(G1_BLK, 1) void k_gemm1(const float* __restrict__ x,
                                                     const float* __restrict__ W1, int n)
{
    extern __shared__ float sm[];
    float* w1s = sm;                   // [KPAD][16]        92160 B
    float* xs  = sm + KPAD * F1;       // [2][KT][ROWP]     99584 B
    const int tid  = threadIdx.x;
    const int lane = tid & 31;
    const int wid  = tid >> 5;
    const int row0 = blockIdx.x * G1_RT;

    for (int i = tid; i < KPAD * F1; i += G1_BLK)
        w1s[i] = (i < F_IN * F1) ? W1[i] : 0.0f;

    // staging: warp w loads rows w*32+i (i=0..31), lane -> k. Coalesced 128B.
    const int srow = row0 + wid * 32;
    float stage[32];

    #pragma unroll
    for (int i = 0; i < 32; ++i) {      // prologue: tile 0
        int gr = srow + i;
        stage[i] = (gr < n && lane < F_IN) ? x[(size_t)gr * F_IN + lane] : 0.0f;
    }

    unsigned long long acc[8];
    #pragma unroll
    for (int j = 0; j < 8; ++j) acc[j] = 0ULL;

    for (int t = 0; t < NT; ++t) {
        float* buf = xs + (t & 1) * (KT * ROWP);
        __syncthreads();                           // prior compute on buf done
        #pragma unroll
        for (int i = 0; i < 32; ++i)
            buf[lane * ROWP + wid * 32 + i] = stage[i];
        __syncthreads();                           // tile visible
        if (t + 1 < NT) {
            int k0 = (t + 1) * KT;
            #pragma unroll
            for (int i = 0; i < 32; ++i) {
                int gr = srow + i;
                int gk = k0 + lane;
                stage[i] = (gr < n && gk < F_IN) ? x[(size_t)gr * F_IN + gk] : 0.0f;
            }
        }
        const float* wrow = w1s + t * KT * F1;
        #pragma unroll
        for (int k = 0; k < KT; ++k) {
            const ulonglong2* wp = (const ulonglong2*)(wrow + k * F1);
            ulonglong2 wa = wp[0], wb = wp[1], wc = wp[2], wd = wp[3];
            float xv = buf[k * ROWP + tid];
            unsigned long long xx;
            asm("mov.b64 %0, {%1, %1};" : "=l"(xx) : "f"(xv));
            FMA2(acc[0], wa.x, xx, acc[0]);
            FMA2(acc[1], wa.y, xx, acc[1]);
            FMA2(acc[2], wb.x, xx, acc[2]);
            FMA2(acc[3], wb.y, xx, acc[3]);
            FMA2(acc[4], wc.x, xx, acc[4]);
            FMA2(acc[5], wc.y, xx, acc[5]);
            FMA2(acc[6], wd.x, xx, acc[6]);
            FMA2(acc[7], wd.y, xx, acc[7]);
        }
    }

    int row = row0 + tid;
    if (row < n) {
        float di = g_dinv[row];
        float4* hp = (float4*)(g_hs1 + (size_t)row * 16);
        #pragma unroll
        for (int q = 0; q < 4; ++q) {
            union { unsigned long long u; float2 f; } a, b;
            a.u = acc[2 * q]; b.u = acc[2 * q + 1];
            hp[q] = make_float4(a.f.x * di, a.f.y * di, b.f.x * di, b.f.y * di);
        }
    }
}

// ---------------- gather L1 + bias/ReLU + layer2 GEMM (fused) ----------------
__global__ __launch_bounds__(256) void k_gather16(const float* __restrict__ b1,
                                                  const float* __restrict__ W2, int n) {
    __shared__ float w2s[F1 * F2];
    if (threadIdx.x < F1 * F2) w2s[threadIdx.x] = W2[threadIdx.x];
    __syncthreads();

    int wid  = threadIdx.x >> 5;
    int lane = threadIdx.x & 31;
    int d    = blockIdx.x * 8 + wid;
    if (d >= n) return;

    int base = g_off[d];
    int cnt  = g_cnt[d];
    int grp  = lane >> 2;
    int col  = lane & 3;

    float4 acc = make_float4(0.f, 0.f, 0.f, 0.f);
    for (int it = grp; it < cnt; it += 8) {
        int s = g_srcs[base + it];
        float4 v = ((const float4*)(g_hs1 + (size_t)s * 16))[col];
        acc.x += v.x; acc.y += v.y; acc.z += v.z; acc.w += v.w;
    }
    __syncwarp();
    #pragma unroll
    for (int o = 16; o >= 4; o >>= 1) {
        acc.x += __shfl_xor_sync(0xffffffffu, acc.x, o);
        acc.y += __shfl_xor_sync(0xffffffffu, acc.y, o);
        acc.z += __shfl_xor_sync(0xffffffffu, acc.z, o);
        acc.w += __shfl_xor_sync(0xffffffffu, acc.w, o);
    }
    float  di   = g_dinv[d];
    float4 self = ((const float4*)(g_hs1 + (size_t)d * 16))[col];
    float4 b    = __ldg((const float4*)b1 + col);
    float4 o;
    o.x = fmaxf(fmaf(di, acc.x + self.x, b.x), 0.f);
    o.y = fmaxf(fmaf(di, acc.y + self.y, b.y), 0.f);
    o.z = fmaxf(fmaf(di, acc.z + self.z, b.z), 0.f);
    o.w = fmaxf(fmaf(di, acc.w + self.w, b.w), 0.f);

    float a[F1];
    #pragma unroll
    for (int j = 0; j < F1; ++j) {
        float c;
        switch (j & 3) { case 0: c = o.x; break; case 1: c = o.y; break;
                         case 2: c = o.z; break; default: c = o.w; }
        a[j] = __shfl_sync(0xffffffffu, c, j >> 2);
    }
    if (lane < 8) {
        float v = 0.f;
        if (lane < 7) {
            float h = 0.f;
            #pragma unroll
            for (int j = 0; j < F1; ++j) h = fmaf(a[j], w2s[j * F2 + lane], h);
            v = h * di;
        }
        g_hs2[(size_t)d * 8 + lane] = v;
    }
}

// ---------------- gather L2 + bias + log_softmax (fused) ----------------
__global__ __launch_bounds__(256) void k_gather8f(const float* __restrict__ b2,
                                                  float* __restrict__ out, int n) {
    int wid  = threadIdx.x >> 5;
    int lane = threadIdx.x & 31;
    int d    = blockIdx.x * 8 + wid;
    if (d >= n) return;

    int base = g_off[d];
    int cnt  = g_cnt[d];
    int grp  = lane >> 1;
    int half = lane & 1;

    float4 acc = make_float4(0.f, 0.f, 0.f, 0.f);
    for (int it = grp; it < cnt; it += 16) {
        int s = g_srcs[base + it];
        float4 v = ((const float4*)(g_hs2 + (size_t)s * 8))[half];
        acc.x += v.x; acc.y += v.y; acc.z += v.z; acc.w += v.w;
    }
    __syncwarp();
    #pragma unroll
    for (int o = 16; o >= 2; o >>= 1) {
        acc.x += __shfl_down_sync(0xffffffffu, acc.x, o);
        acc.y += __shfl_down_sync(0xffffffffu, acc.y, o);
        acc.z += __shfl_down_sync(0xffffffffu, acc.z, o);
        acc.w += __shfl_down_sync(0xffffffffu, acc.w, o);
    }
    if (lane < 2) {
        float4 self = ((const float4*)(g_hs2 + (size_t)d * 8))[lane];
        acc.x += self.x; acc.y += self.y; acc.z += self.z; acc.w += self.w;
    }
    float hx = __shfl_sync(0xffffffffu, acc.x, 1);
    float hy = __shfl_sync(0xffffffffu, acc.y, 1);
    float hz = __shfl_sync(0xffffffffu, acc.z, 1);
    if (lane == 0) {
        float di = g_dinv[d];
        float v[7] = {acc.x, acc.y, acc.z, acc.w, hx, hy, hz};
        #pragma unroll
        for (int k = 0; k < 7; ++k) v[k] = fmaf(di, v[k], __ldg(b2 + k));
        float m = v[0];
        #pragma unroll
        for (int k = 1; k < 7; ++k) m = fmaxf(m, v[k]);
        float s = 0.f;
        #pragma unroll
        for (int k = 0; k < 7; ++k) s += expf(v[k] - m);
        float l = m + logf(s);
        float* op = out + (size_t)d * 7;
        #pragma unroll
        for (int k = 0; k < 7; ++k) op[k] = v[k] - l;
    }
}

// ---------------- launch (serial; overlap regressed in R9) ----------------
extern "C" void kernel_launch(void* const* d_in, const int* in_sizes, int n_in,
                              void* d_out, int out_size)
{
    const float* x  = (const float*)d_in[0];
    const int*   ei = (const int*)d_in[1];     // int32 (JAX x64 disabled)
    const float* W1 = (const float*)d_in[2];
    const float* b1 = (const float*)d_in[3];
    const float* W2 = (const float*)d_in[4];
    const float* b2 = (const float*)d_in[5];

    int n = in_sizes[0] / F_IN;   // 50000
    int E = in_sizes[1] / 2;      // 1600000

    const int smem1 = (KPAD * F1 + 2 * KT * ROWP) * (int)sizeof(float);  // 191744 B
    cudaFuncSetAttribute(k_gemm1, cudaFuncAttributeMaxDynamicSharedMemorySize, smem1);

    void* p_cnt = 0; void* p_total = 0;
    cudaGetSymbolAddress(&p_cnt, g_cnt);
    cudaGetSymbolAddress(&p_total, g_total);

    int nb256 = (n + 255) / 256;
    int e4b   = ((E >> 2) + 255) / 256;
    int gwarp = (n + 7) / 8;

    cudaMemsetAsync(p_cnt, 0, NMAX * sizeof(int), 0);
    cudaMemsetAsync(p_total, 0, sizeof(int), 0);
    k_count   <<<e4b, 256>>>(ei, E);
    k_alloc   <<<nb256, 256>>>(n);
    k_gemm1   <<<G1_GRID, G1_BLK, smem1>>>(x, W1, n);
    k_fill    <<<e4b, 256>>>(ei, E);
    k_gather16<<<gwarp, 256>>>(b1, W2, n);
    k_gather8f<<<gwarp, 256>>>(b2, (float*)d_out, n);
}

// round 13
// speedup vs baseline: 1.0952x; 1.0818x over previous
#include <cuda_runtime.h>

#define F_IN 1433
#define F1   16
#define F2   7
#define NMAX 50000
#define EMAX 1664000

// ---------------- scratch (no allocations allowed) ----------------
__device__ __align__(16) int   g_cnt [NMAX];     // in-degree (real edges)
__device__ __align__(16) int   g_off [NMAX];     // CSR bucket start
__device__ __align__(16) int   g_cur [NMAX];     // fill cursor
__device__             int     g_total;          // bucket allocator
__device__ __align__(16) int   g_srcs[EMAX];     // CSR: src per in-edge, bucketed by dst
__device__ __align__(16) float g_dinv[NMAX];
__device__ __align__(16) float g_hs1 [NMAX * 16];  // (x@W1)*dinv, accumulated by 2 K-half blocks
__device__ __align__(16) float g_hs2 [NMAX * 8];   // (a1@W2)*dinv (gather source L2, col7=0)

// packed fp32x2 FMA (Blackwell; only reachable via PTX)
#define FMA2(d,a,b,c) asm("fma.rn.f32x2 %0, %1, %2, %3;" : "=l"(d) : "l"(a), "l"(b), "l"(c))

// ---------------- CSR build ----------------
__global__ __launch_bounds__(256) void k_count(const int* __restrict__ ei, int E) {
    int i  = blockIdx.x * blockDim.x + threadIdx.x;
    int E4 = E >> 2;
    if (i < E4) {
        int4 d = ((const int4*)(ei + E))[i];
        atomicAdd(&g_cnt[d.x], 1);
        atomicAdd(&g_cnt[d.y], 1);
        atomicAdd(&g_cnt[d.z], 1);
        atomicAdd(&g_cnt[d.w], 1);
    }
    if (i == 0)
        for (int e = E4 << 2; e < E; ++e) atomicAdd(&g_cnt[ei[E + e]], 1);
}

__global__ __launch_bounds__(256) void k_alloc(int n) {
    int i    = blockIdx.x * blockDim.x + threadIdx.x;
    int lane = threadIdx.x & 31;
    int c    = (i < n) ? g_cnt[i] : 0;
    int incl = c;
    #pragma unroll
    for (int o = 1; o < 32; o <<= 1) {
        int v = __shfl_up_sync(0xffffffffu, incl, o);
        if (lane >= o) incl += v;
    }
    int tot  = __shfl_sync(0xffffffffu, incl, 31);
    int base = 0;
    if (lane == 31) base = atomicAdd(&g_total, tot);
    base = __shfl_sync(0xffffffffu, base, 31);
    if (i < n) {
        int off = base + incl - c;
        g_off[i] = off;
        g_cur[i] = off;
        g_dinv[i] = rsqrtf((float)(c + 1));   // +1 self loop
    }
}

__global__ __launch_bounds__(256) void k_fill(const int* __restrict__ ei, int E) {
    int i  = blockIdx.x * blockDim.x + threadIdx.x;
    int E4 = E >> 2;
    if (i < E4) {
        int4 s = ((const int4*)ei)[i];
        int4 d = ((const int4*)(ei + E))[i];
        int p0 = atomicAdd(&g_cur[d.x], 1);
        int p1 = atomicAdd(&g_cur[d.y], 1);
        int p2 = atomicAdd(&g_cur[d.z], 1);
        int p3 = atomicAdd(&g_cur[d.w], 1);
        g_srcs[p0] = s.x; g_srcs[p1] = s.y; g_srcs[p2] = s.z; g_srcs[p3] = s.w;
    }
    if (i == 0)
        for (int e = E4 << 2; e < E; ++e) {
            int p = atomicAdd(&g_cur[ei[E + e]], 1);
            g_srcs[p] = ei[e];
        }
}

// ---------------- GEMM1 v4: K-split, 2 blocks/SM ----------------
// grid = 296 = 148 row-blocks x 2 K-halves (single wave, 2 blocks/SM).
// Each block: its 720-k half of W in smem (46KB) + double-buffered transposed
// x tile xs[2][16][357] (45.7KB). Partial result *dinv atomically added to g_hs1.
#define G1_BLK   352          // 11 warps
#define G1_RT    338          // rows per block (148*338 = 50024 >= 50000)
#define G1_GRID  296
#define G1_KT    16
#define G1_TILES 45           // 45*16 = 720 k per half
#define G1_HALF  720
#define G1_ROWP  357          // bank stride 5 -> near-conflict-free both ways

__global__ __launch_bounds__(G1_BLK, 2) void k_gemm1(const float* __restrict__ x,
                                                     const float* __restrict__ W1, int n)
{
    extern __shared__ float sm[];
    float* w1s = sm;                        // [720][16]     46080 B
    float* xs  = sm + G1_HALF * F1;         // [2][16][357]  45696 B
    const int tid   = threadIdx.x;
    const int lane  = tid & 31;
    const int wid   = tid >> 5;
    const int rb    = blockIdx.x >> 1;
    const int kb    = blockIdx.x & 1;
    const int kbase = kb * G1_HALF;
    const int row0  = rb * G1_RT;

    for (int i = tid; i < G1_HALF * F1; i += G1_BLK) {
        int gk = kbase + (i >> 4);
        w1s[i] = (gk < F_IN) ? W1[gk * F1 + (i & 15)] : 0.0f;
    }

    // staging: warp wid covers local rows [wid*32, wid*32+32); per step i,
    // lanes 0-15 -> row 2i, lanes 16-31 -> row 2i+1; (lane&15) -> k.
    const int lrow0 = wid * 32 + (lane >> 4);
    const int kofs  = lane & 15;
    float stage[16];

    #pragma unroll
    for (int i = 0; i < 16; ++i) {          // prologue: tile 0
        int gr = row0 + lrow0 + 2 * i;
        int gk = kbase + kofs;
        stage[i] = (gr < n && gk < F_IN) ? x[(size_t)gr * F_IN + gk] : 0.0f;
    }

    unsigned long long acc[8];
    #pragma unroll
    for (int j = 0; j < 8; ++j) acc[j] = 0ULL;

    for (int t = 0; t < G1_TILES; ++t) {
        float* buf = xs + (t & 1) * (G1_KT * G1_ROWP);
        __syncthreads();
        #pragma unroll
        for (int i = 0; i < 16; ++i)
            buf[kofs * G1_ROWP + lrow0 + 2 * i] = stage[i];
        __syncthreads();
        if (t + 1 < G1_TILES) {
            int k0 = (t + 1) * G1_KT;
            #pragma unroll
            for (int i = 0; i < 16; ++i) {
                int gr = row0 + lrow0 + 2 * i;
                int gk = kbase + k0 + kofs;
                stage[i] = (gr < n && gk < F_IN) ? x[(size_t)gr * F_IN + gk] : 0.0f;
            }
        }
        const float* wrow = w1s + t * G1_KT * F1;
        #pragma unroll
        for (int k = 0; k < G1_KT; ++k) {
            const ulonglong2* wp = (const ulonglong2*)(wrow + k * F1);
            ulonglong2 wa = wp[0], wb = wp[1], wc = wp[2], wd = wp[3];
            float xv = buf[k * G1_ROWP + tid];
            unsigned long long xx;
            asm("mov.b64 %0, {%1, %1};" : "=l"(xx) : "f"(xv));
            FMA2(acc[0], wa.x, xx, acc[0]);
            FMA2(acc[1], wa.y, xx, acc[1]);
            FMA2(acc[2], wb.x, xx, acc[2]);
            FMA2(acc[3], wb.y, xx, acc[3]);
            FMA2(acc[4], wc.x, xx, acc[4]);
            FMA2(acc[5], wc.y, xx, acc[5]);
            FMA2(acc[6], wd.x, xx, acc[6]);
            FMA2(acc[7], wd.y, xx, acc[7]);
        }
    }

    int row = row0 + tid;
    if (tid < G1_RT && row < n) {
        float di = g_dinv[row];
        float* hp = g_hs1 + (size_t)row * 16;
        #pragma unroll
        for (int j = 0; j < 8; ++j) {
            union { unsigned long long u; float2 f; } cv;
            cv.u = acc[j];
            atomicAdd(hp + 2 * j,     cv.f.x * di);
            atomicAdd(hp + 2 * j + 1, cv.f.y * di);
        }
    }
}

// ---------------- gather L1 + bias/ReLU + layer2 GEMM (fused) ----------------
__global__ __launch_bounds__(256) void k_gather16(const float* __restrict__ b1,
                                                  const float* __restrict__ W2, int n) {
    __shared__ float w2s[F1 * F2];
    if (threadIdx.x < F1 * F2) w2s[threadIdx.x] = W2[threadIdx.x];
    __syncthreads();

    int wid  = threadIdx.x >> 5;
    int lane = threadIdx.x & 31;
    int d    = blockIdx.x * 8 + wid;
    if (d >= n) return;

    int base = g_off[d];
    int cnt  = g_cnt[d];
    int grp  = lane >> 2;
    int col  = lane & 3;

    float4 acc = make_float4(0.f, 0.f, 0.f, 0.f);
    for (int it = grp; it < cnt; it += 8) {
        int s = g_srcs[base + it];
        float4 v = ((const float4*)(g_hs1 + (size_t)s * 16))[col];
        acc.x += v.x; acc.y += v.y; acc.z += v.z; acc.w += v.w;
    }
    __syncwarp();
    #pragma unroll
    for (int o = 16; o >= 4; o >>= 1) {
        acc.x += __shfl_xor_sync(0xffffffffu, acc.x, o);
        acc.y += __shfl_xor_sync(0xffffffffu, acc.y, o);
        acc.z += __shfl_xor_sync(0xffffffffu, acc.z, o);
        acc.w += __shfl_xor_sync(0xffffffffu, acc.w, o);
    }
    float  di   = g_dinv[d];
    float4 self = ((const float4*)(g_hs1 + (size_t)d * 16))[col];
    float4 b    = __ldg((const float4*)b1 + col);
    float4 o;
    o.x = fmaxf(fmaf(di, acc.x + self.x, b.x), 0.f);
    o.y = fmaxf(fmaf(di, acc.y + self.y, b.y), 0.f);
    o.z = fmaxf(fmaf(di, acc.z + self.z, b.z), 0.f);
    o.w = fmaxf(fmaf(di, acc.w + self.w, b.w), 0.f);

    float a[F1];
    #pragma unroll
    for (int j = 0; j < F1; ++j) {
        float c;
        switch (j & 3) { case 0: c = o.x; break; case 1: c = o.y; break;
                         case 2: c = o.z; break; default: c = o.w; }
        a[j] = __shfl_sync(0xffffffffu, c, j >> 2);
    }
    if (lane < 8) {
        float v = 0.f;
        if (lane < 7) {
            float h = 0.f;
            #pragma unroll
            for (int j = 0; j < F1; ++j) h = fmaf(a[j], w2s[j * F2 + lane], h);
            v = h * di;
        }
        g_hs2[(size_t)d * 8 + lane] = v;
    }
}

// ---------------- gather L2 + bias + log_softmax (fused) ----------------
__global__ __launch_bounds__(256) void k_gather8f(const float* __restrict__ b2,
                                                  float* __restrict__ out, int n) {
    int wid  = threadIdx.x >> 5;
    int lane = threadIdx.x & 31;
    int d    = blockIdx.x * 8 + wid;
    if (d >= n) return;

    int base = g_off[d];
    int cnt  = g_cnt[d];
    int grp  = lane >> 1;
    int half = lane & 1;

    float4 acc = make_float4(0.f, 0.f, 0.f, 0.f);
    for (int it = grp; it < cnt; it += 16) {
        int s = g_srcs[base + it];
        float4 v = ((const float4*)(g_hs2 + (size_t)s * 8))[half];
        acc.x += v.x; acc.y += v.y; acc.z += v.z; acc.w += v.w;
    }
    __syncwarp();
    #pragma unroll
    for (int o = 16; o >= 2; o >>= 1) {
        acc.x += __shfl_down_sync(0xffffffffu, acc.x, o);
        acc.y += __shfl_down_sync(0xffffffffu, acc.y, o);
        acc.z += __shfl_down_sync(0xffffffffu, acc.z, o);
        acc.w += __shfl_down_sync(0xffffffffu, acc.w, o);
    }
    if (lane < 2) {
        float4 self = ((const float4*)(g_hs2 + (size_t)d * 8))[lane];
        acc.x += self.x; acc.y += self.y; acc.z += self.z; acc.w += self.w;
    }
    float hx = __shfl_sync(0xffffffffu, acc.x, 1);
    float hy = __shfl_sync(0xffffffffu, acc.y, 1);
    float hz = __shfl_sync(0xffffffffu, acc.z, 1);
    if (lane == 0) {
        float di = g_dinv[d];
        float v[7] = {acc.x, acc.y, acc.z, acc.w, hx, hy, hz};
        #pragma unroll
        for (int k = 0; k < 7; ++k) v[k] = fmaf(di, v[k], __ldg(b2 + k));
        float m = v[0];
        #pragma unroll
        for (int k = 1; k < 7; ++k) m = fmaxf(m, v[k]);
        float s = 0.f;
        #pragma unroll
        for (int k = 0; k < 7; ++k) s += expf(v[k] - m);
        float l = m + logf(s);
        float* op = out + (size_t)d * 7;
        #pragma unroll
        for (int k = 0; k < 7; ++k) op[k] = v[k] - l;
    }
}

// ---------------- launch ----------------
extern "C" void kernel_launch(void* const* d_in, const int* in_sizes, int n_in,
                              void* d_out, int out_size)
{
    const float* x  = (const float*)d_in[0];
    const int*   ei = (const int*)d_in[1];     // int32 (JAX x64 disabled)
    const float* W1 = (const float*)d_in[2];
    const float* b1 = (const float*)d_in[3];
    const float* W2 = (const float*)d_in[4];
    const float* b2 = (const float*)d_in[5];

    int n = in_sizes[0] / F_IN;   // 50000
    int E = in_sizes[1] / 2;      // 1600000

    const int smem1 = (G1_HALF * F1 + 2 * G1_KT * G1_ROWP) * (int)sizeof(float);  // 91776 B
    cudaFuncSetAttribute(k_gemm1, cudaFuncAttributeMaxDynamicSharedMemorySize, smem1);

    void* p_cnt = 0; void* p_total = 0; void* p_hs1 = 0;
    cudaGetSymbolAddress(&p_cnt, g_cnt);
    cudaGetSymbolAddress(&p_total, g_total);
    cudaGetSymbolAddress(&p_hs1, g_hs1);

    int nb256 = (n + 255) / 256;
    int e4b   = ((E >> 2) + 255) / 256;
    int gwarp = (n + 7) / 8;

    cudaMemsetAsync(p_cnt, 0, NMAX * sizeof(int), 0);
    cudaMemsetAsync(p_total, 0, sizeof(int), 0);
    cudaMemsetAsync(p_hs1, 0, NMAX * 16 * sizeof(float), 0);
    k_count   <<<e4b, 256>>>(ei, E);             // kernel 1
    k_alloc   <<<nb256, 256>>>(n);               // kernel 2
    k_fill    <<<e4b, 256>>>(ei, E);             // kernel 3
    k_gemm1   <<<G1_GRID, G1_BLK, smem1>>>(x, W1, n);  // kernel 4 -> ncu sample
    k_gather16<<<gwarp, 256>>>(b1, W2, n);       // kernel 5
    k_gather8f<<<gwarp, 256>>>(b2, (float*)d_out, n);  // kernel 6
}